// round 15
// baseline (speedup 1.0000x reference)
#include <cuda_runtime.h>
#include <math.h>

#define BB 4
#define TT 2048
#define DD 256
#define HD 64
#define LL 2
#define MMR (BB*TT)
#define NQ 128

__device__ __align__(16) float g_x  [MMR*DD];
__device__ __align__(16) float g_lnb[MMR*DD];
__device__ __align__(16) float g_qkv[MMR*3*DD];
__device__ __align__(16) float g_att[MMR*DD];
__device__ __align__(16) float g_ffh[MMR*4*DD];
__device__ __align__(16) float g_sel[BB*NQ*DD];
__device__ __align__(16) float g_bits[BB*NQ];
__device__ __align__(16) float g_zero[TT];
__device__ float g_invf[32];

__device__ __forceinline__ float geluf(float v) {
    return 0.5f * v * (1.0f + erff(v * 0.70710678118654752f));
}

__device__ __forceinline__ void cp16(void* smem_dst, const void* gsrc) {
    unsigned s = (unsigned)__cvta_generic_to_shared(smem_dst);
    asm volatile("cp.async.cg.shared.global [%0], [%1], 16;" :: "r"(s), "l"(gsrc));
}
#define CP_COMMIT() asm volatile("cp.async.commit_group;")
#define CP_WAIT0()  asm volatile("cp.async.wait_group 0;")
#define CP_WAIT1()  asm volatile("cp.async.wait_group 1;")

__device__ __forceinline__ void mma8(float* d, const unsigned* a, unsigned b0, unsigned b1) {
    asm volatile(
        "mma.sync.aligned.m16n8k8.row.col.f32.tf32.tf32.f32 "
        "{%0,%1,%2,%3},{%4,%5,%6,%7},{%8,%9},{%0,%1,%2,%3};"
        : "+f"(d[0]), "+f"(d[1]), "+f"(d[2]), "+f"(d[3])
        : "r"(a[0]), "r"(a[1]), "r"(a[2]), "r"(a[3]), "r"(b0), "r"(b1));
}

__global__ void k_init_tab() {
    int t = threadIdx.x;
    g_invf[t] = (float)exp(-0.28782313662425572 * (double)t);
}

__global__ void __launch_bounds__(256) k_embed(const int* __restrict__ tok,
                                               const float* __restrict__ emb,
                                               float* __restrict__ x) {
    int i = blockIdx.x * 256 + threadIdx.x;
    x[i] = emb[tok[i >> 8] * DD + (i & 255)];
}

/* warp-per-row layernorm: 8 rows per 256-thread block, shuffle-only */
__global__ void __launch_bounds__(256) k_ln(const float* __restrict__ x,
                                            const float* __restrict__ w,
                                            const float* __restrict__ bia,
                                            float* __restrict__ y) {
    const int warp = threadIdx.x >> 5, lane = threadIdx.x & 31;
    const int row = blockIdx.x * 8 + warp;
    const float* xr = x + (size_t)row * DD;
    float4 v0 = *(const float4*)(xr + lane * 4);
    float4 v1 = *(const float4*)(xr + 128 + lane * 4);
    float s = v0.x+v0.y+v0.z+v0.w + v1.x+v1.y+v1.z+v1.w;
    #pragma unroll
    for (int m = 16; m; m >>= 1) s += __shfl_xor_sync(0xffffffffu, s, m);
    float mean = s * (1.0f / DD);
    float a0 = v0.x-mean, a1 = v0.y-mean, a2 = v0.z-mean, a3 = v0.w-mean;
    float a4 = v1.x-mean, a5 = v1.y-mean, a6 = v1.z-mean, a7 = v1.w-mean;
    float q = a0*a0+a1*a1+a2*a2+a3*a3+a4*a4+a5*a5+a6*a6+a7*a7;
    #pragma unroll
    for (int m = 16; m; m >>= 1) q += __shfl_xor_sync(0xffffffffu, q, m);
    float rs = rsqrtf(q * (1.0f / DD) + 1e-5f);
    float4 w0 = *(const float4*)(w + lane * 4);
    float4 w1 = *(const float4*)(w + 128 + lane * 4);
    float4 b0 = *(const float4*)(bia + lane * 4);
    float4 b1 = *(const float4*)(bia + 128 + lane * 4);
    float* yr = y + (size_t)row * DD;
    *(float4*)(yr + lane * 4) =
        make_float4(a0*rs*w0.x+b0.x, a1*rs*w0.y+b0.y, a2*rs*w0.z+b0.z, a3*rs*w0.w+b0.w);
    *(float4*)(yr + 128 + lane * 4) =
        make_float4(a4*rs*w1.x+b1.x, a5*rs*w1.y+b1.y, a6*rs*w1.z+b1.z, a7*rs*w1.w+b1.w);
}

/* transpose [T,D] -> [D,T] per batch */
__global__ void __launch_bounds__(256) k_tr(const float* __restrict__ A,
                                            float* __restrict__ B) {
    __shared__ float t[32][33];
    const float* Ab = A + (size_t)blockIdx.z * TT * DD;
    float* Bb = B + (size_t)blockIdx.z * DD * TT;
    int t0 = blockIdx.x * 32, d0 = blockIdx.y * 32;
    int x = threadIdx.x & 31, y = threadIdx.x >> 5;
    #pragma unroll
    for (int i = 0; i < 32; i += 8)
        t[y + i][x] = Ab[(size_t)(t0 + y + i) * DD + d0 + x];
    __syncthreads();
    #pragma unroll
    for (int i = 0; i < 32; i += 8)
        Bb[(size_t)(d0 + y + i) * TT + t0 + x] = t[x][y + i];
}

/* ---- tf32 tensor-core GEMM, 2-stage cp.async (R12 schedule), batched ----
   C[M,N] = A[M,K] @ W[K,N] + bias ; EPI 0=bias 1=+gelu 2=+residual */
#define GS(TM) ((2 * ((TM)*36 + 32*136)) * 4)
template<int EPI, int TM>
__global__ void __launch_bounds__(256, 2) k_gemm_tc(
        const float* __restrict__ A, const float* __restrict__ W,
        const float* __restrict__ bias, const float* __restrict__ res,
        float* __restrict__ C, int N, int K,
        long long sA, long long sW, long long sC) {
    A += (long long)blockIdx.z * sA;
    W += (long long)blockIdx.z * sW;
    C += (long long)blockIdx.z * sC;
    extern __shared__ unsigned sg[];
    const int GA_W = TM * 36, GW_W = 32 * 136;
    unsigned* As0 = sg;
    unsigned* Ws0 = sg + 2 * GA_W;
    const int m0 = blockIdx.y * TM, n0 = blockIdx.x * 128;
    constexpr int MI = TM / 32;
    float d[MI * 4][4] = {};
    const int tid = threadIdx.x, warp = tid >> 5, lane = tid & 31;
    const int g = lane >> 2, tig = lane & 3;
    const int wm = (warp & 1) * (TM / 2), wn = (warp >> 1) * 32;
    const int cw = lane * 4;

    const int T = K >> 5;
    #pragma unroll
    for (int it = 0; it < TM / 32; it++) {
        int r = (TM == 128) ? (warp * 16 + (lane >> 3) + it * 4) : ((tid >> 3) + it * 32);
        int ca = (TM == 128) ? ((lane & 7) * 4) : ((tid & 7) * 4);
        cp16(&As0[r * 36 + ca], A + (size_t)(m0 + r) * K + ca);
    }
    #pragma unroll
    for (int it = 0; it < 4; it++) {
        int kw = warp + it * 8;
        cp16(&Ws0[kw * 136 + cw], W + (size_t)kw * N + n0 + cw);
    }
    CP_COMMIT();
    for (int t = 0; t < T; t++) {
        if (t + 1 < T) {
            int k0 = (t + 1) << 5, st = (t + 1) & 1;
            #pragma unroll
            for (int it = 0; it < TM / 32; it++) {
                int r = (TM == 128) ? (warp * 16 + (lane >> 3) + it * 4) : ((tid >> 3) + it * 32);
                int ca = (TM == 128) ? ((lane & 7) * 4) : ((tid & 7) * 4);
                cp16(&As0[st * GA_W + r * 36 + ca], A + (size_t)(m0 + r) * K + k0 + ca);
            }
            #pragma unroll
            for (int it = 0; it < 4; it++) {
                int kw = warp + it * 8;
                cp16(&Ws0[st * GW_W + kw * 136 + cw], W + (size_t)(k0 + kw) * N + n0 + cw);
            }
            CP_COMMIT();
            CP_WAIT1();
        } else {
            CP_WAIT0();
        }
        __syncthreads();
        const unsigned* Ab = As0 + (t & 1) * GA_W;
        const unsigned* Wb = Ws0 + (t & 1) * GW_W;
        #pragma unroll
        for (int ks = 0; ks < 32; ks += 8) {
            unsigned a[MI][4], b[4][2];
            #pragma unroll
            for (int mi = 0; mi < MI; mi++) {
                int m = wm + mi * 16 + g;
                a[mi][0] = Ab[m * 36 + ks + tig];
                a[mi][1] = Ab[(m + 8) * 36 + ks + tig];
                a[mi][2] = Ab[m * 36 + ks + tig + 4];
                a[mi][3] = Ab[(m + 8) * 36 + ks + tig + 4];
            }
            #pragma unroll
            for (int ni = 0; ni < 4; ni++) {
                int n = wn + ni * 8 + g;
                b[ni][0] = Wb[(ks + tig) * 136 + n];
                b[ni][1] = Wb[(ks + tig + 4) * 136 + n];
            }
            #pragma unroll
            for (int mi = 0; mi < MI; mi++)
                #pragma unroll
                for (int ni = 0; ni < 4; ni++)
                    mma8(d[mi * 4 + ni], a[mi], b[ni][0], b[ni][1]);
        }
        __syncthreads();
    }
    #pragma unroll
    for (int mi = 0; mi < MI; mi++) {
        #pragma unroll
        for (int ni = 0; ni < 4; ni++) {
            float* dd = d[mi * 4 + ni];
            int col = n0 + wn + ni * 8 + 2 * tig;
            int r0 = m0 + wm + mi * 16 + g;
            float2 b2 = *(const float2*)(bias + col);
            float2 v0 = make_float2(dd[0] + b2.x, dd[1] + b2.y);
            float2 v1 = make_float2(dd[2] + b2.x, dd[3] + b2.y);
            if (EPI == 1) {
                v0.x = geluf(v0.x); v0.y = geluf(v0.y);
                v1.x = geluf(v1.x); v1.y = geluf(v1.y);
            }
            if (EPI == 2) {
                float2 r0v = *(const float2*)(res + (size_t)r0 * N + col);
                float2 r1v = *(const float2*)(res + (size_t)(r0 + 8) * N + col);
                v0.x += r0v.x; v0.y += r0v.y;
                v1.x += r1v.x; v1.y += r1v.y;
            }
            *(float2*)(C + (size_t)r0 * N + col) = v0;
            *(float2*)(C + (size_t)(r0 + 8) * N + col) = v1;
        }
    }
}

__global__ void __launch_bounds__(256) k_rope(float* __restrict__ qkv) {
    int i = blockIdx.x * 256 + threadIdx.x;
    int p = i & 31, h = (i >> 5) & 3, bt = i >> 7;
    int tpos = bt & (TT - 1);
    float ang = (float)tpos * g_invf[p], sn, cs;
    sincosf(ang, &sn, &cs);
    size_t base = (size_t)bt * (3 * DD) + h * HD;
    float q1 = qkv[base + p],       q2 = qkv[base + 32 + p];
    qkv[base + p]      = q1 * cs - q2 * sn;
    qkv[base + 32 + p] = q2 * cs + q1 * sn;
    float k1 = qkv[base + 256 + p], k2 = qkv[base + 288 + p];
    qkv[base + 256 + p] = k1 * cs - k2 * sn;
    qkv[base + 288 + p] = k2 * cs + k1 * sn;
}

/* ---- tf32 flash attention: 128-row q-tiles, 256 thr / 8 warps ----
   Warp w owns q-rows [16w,16w+16). K/V 64-row tiles double-buffered.
   Block handles q-tile pair (p, 15-p): constant 34 kb-tiles. */
#define QST 68
#define VST 72
#define ATT_Q  0
#define ATT_P  (128*QST)
#define ATT_K  (2*128*QST)              /* 2 x [64][QST] */
#define ATT_V  (ATT_K + 2*64*QST)       /* 2 x [64][VST] */
#define ATTC_SMEM ((ATT_V + 2*64*VST) * 4)
__global__ void __launch_bounds__(256) k_attn_tc(const float* __restrict__ qkv,
                                                 float* __restrict__ outp) {
    extern __shared__ unsigned smu[];
    unsigned* Qs = smu + ATT_Q;
    unsigned* Ps = smu + ATT_P;
    unsigned* Ks = smu + ATT_K;
    unsigned* Vs = smu + ATT_V;
    const int pp = blockIdx.x;
    const int b = blockIdx.y >> 2, h = blockIdx.y & 3;
    const int tid = threadIdx.x, warp = tid >> 5, lane = tid & 31;
    const int g = lane >> 2, tig = lane & 3;
    const int wm = warp * 16;
    const int r0 = wm + g, r1 = wm + g + 8;
    const size_t ROW = 3 * DD;
    const int lr = tid >> 4, lc4 = (tid & 15) << 2;

    for (int qsel = 0; qsel < 2; qsel++) {
        const int qi = qsel ? (15 - pp) : pp;
        const int KBE = 2 * qi + 1;            /* last kb index */
        const float* qb = qkv + ((size_t)(b * TT + qi * 128)) * ROW + h * HD;
        #pragma unroll
        for (int it = 0; it < 8; it++) {
            int r = lr + it * 16;
            cp16(&Qs[r * QST + lc4], qb + (size_t)r * ROW + lc4);
        }
        CP_COMMIT();
        {
            const float* kbp = qkv + ((size_t)(b * TT)) * ROW + DD + h * HD;
            #pragma unroll
            for (int it = 0; it < 4; it++) {
                int r = lr + it * 16;
                cp16(&Ks[r * QST + lc4], kbp + (size_t)r * ROW + lc4);
                cp16(&Vs[r * VST + lc4], kbp + DD + (size_t)r * ROW + lc4);
            }
            CP_COMMIT();
        }
        float o[8][4] = {};
        float mrow0 = -1e30f, mrow1 = -1e30f, lrow0 = 0.0f, lrow1 = 0.0f;

        for (int kb = 0; kb <= KBE; kb++) {
            if (kb + 1 <= KBE) {
                const float* kbp = qkv + ((size_t)(b * TT + (kb + 1) * 64)) * ROW + DD + h * HD;
                unsigned* Kd = Ks + ((kb + 1) & 1) * 64 * QST;
                unsigned* Vd = Vs + ((kb + 1) & 1) * 64 * VST;
                #pragma unroll
                for (int it = 0; it < 4; it++) {
                    int r = lr + it * 16;
                    cp16(&Kd[r * QST + lc4], kbp + (size_t)r * ROW + lc4);
                    cp16(&Vd[r * VST + lc4], kbp + DD + (size_t)r * ROW + lc4);
                }
                CP_COMMIT();
                CP_WAIT1();
            } else {
                CP_WAIT0();
            }
            __syncthreads();
            const unsigned* Kb = Ks + (kb & 1) * 64 * QST;
            const unsigned* Vb = Vs + (kb & 1) * 64 * VST;

            float s[8][4] = {};
            #pragma unroll
            for (int ks = 0; ks < 64; ks += 8) {
                unsigned a[4];
                a[0] = Qs[r0 * QST + ks + tig];
                a[1] = Qs[r1 * QST + ks + tig];
                a[2] = Qs[r0 * QST + ks + tig + 4];
                a[3] = Qs[r1 * QST + ks + tig + 4];
                #pragma unroll
                for (int nt = 0; nt < 8; nt++) {
                    unsigned b0 = Kb[(nt*8 + g) * QST + ks + tig];
                    unsigned b1 = Kb[(nt*8 + g) * QST + ks + tig + 4];
                    mma8(s[nt], a, b0, b1);
                }
            }

            /* causal: mask if c > off + r  (off = qi*128 - kb*64; skip if off>=64) */
            const int off = qi * 128 - kb * 64;
            #pragma unroll
            for (int nt = 0; nt < 8; nt++) {
                int c0 = nt * 8 + 2 * tig, c1 = c0 + 1;
                s[nt][0] *= 0.125f; s[nt][1] *= 0.125f;
                s[nt][2] *= 0.125f; s[nt][3] *= 0.125f;
                if (off < 64) {
                    if (c0 > off + r0) s[nt][0] = -1e30f;
                    if (c1 > off + r0) s[nt][1] = -1e30f;
                    if (c0 > off + r1) s[nt][2] = -1e30f;
                    if (c1 > off + r1) s[nt][3] = -1e30f;
                }
            }
            float rm0 = -1e30f, rm1 = -1e30f;
            #pragma unroll
            for (int nt = 0; nt < 8; nt++) {
                rm0 = fmaxf(rm0, fmaxf(s[nt][0], s[nt][1]));
                rm1 = fmaxf(rm1, fmaxf(s[nt][2], s[nt][3]));
            }
            rm0 = fmaxf(rm0, __shfl_xor_sync(0xffffffffu, rm0, 1));
            rm0 = fmaxf(rm0, __shfl_xor_sync(0xffffffffu, rm0, 2));
            rm1 = fmaxf(rm1, __shfl_xor_sync(0xffffffffu, rm1, 1));
            rm1 = fmaxf(rm1, __shfl_xor_sync(0xffffffffu, rm1, 2));
            float mn0 = fmaxf(mrow0, rm0), mn1 = fmaxf(mrow1, rm1);
            float corr0 = __expf(mrow0 - mn0), corr1 = __expf(mrow1 - mn1);
            float rs0 = 0.0f, rs1 = 0.0f;
            #pragma unroll
            for (int nt = 0; nt < 8; nt++) {
                s[nt][0] = __expf(s[nt][0] - mn0); rs0 += s[nt][0];
                s[nt][1] = __expf(s[nt][1] - mn0); rs0 += s[nt][1];
                s[nt][2] = __expf(s[nt][2] - mn1); rs1 += s[nt][2];
                s[nt][3] = __expf(s[nt][3] - mn1); rs1 += s[nt][3];
            }
            rs0 += __shfl_xor_sync(0xffffffffu, rs0, 1);
            rs0 += __shfl_xor_sync(0xffffffffu, rs0, 2);
            rs1 += __shfl_xor_sync(0xffffffffu, rs1, 1);
            rs1 += __shfl_xor_sync(0xffffffffu, rs1, 2);
            lrow0 = lrow0 * corr0 + rs0;
            lrow1 = lrow1 * corr1 + rs1;
            mrow0 = mn0; mrow1 = mn1;
            #pragma unroll
            for (int nt = 0; nt < 8; nt++) {
                o[nt][0] *= corr0; o[nt][1] *= corr0;
                o[nt][2] *= corr1; o[nt][3] *= corr1;
            }
            #pragma unroll
            for (int nt = 0; nt < 8; nt++) {
                Ps[r0 * QST + nt*8 + 2*tig]     = __float_as_uint(s[nt][0]);
                Ps[r0 * QST + nt*8 + 2*tig + 1] = __float_as_uint(s[nt][1]);
                Ps[r1 * QST + nt*8 + 2*tig]     = __float_as_uint(s[nt][2]);
                Ps[r1 * QST + nt*8 + 2*tig + 1] = __float_as_uint(s[nt][3]);
            }
            __syncwarp();
            #pragma unroll
            for (int ks = 0; ks < 64; ks += 8) {
                unsigned a[4];
                a[0] = Ps[r0 * QST + ks + tig];
                a[1] = Ps[r1 * QST + ks + tig];
                a[2] = Ps[r0 * QST + ks + tig + 4];
                a[3] = Ps[r1 * QST + ks + tig + 4];
                #pragma unroll
                for (int nt = 0; nt < 8; nt++) {
                    unsigned b0 = Vb[(ks + tig) * VST + nt*8 + g];
                    unsigned b1 = Vb[(ks + tig + 4) * VST + nt*8 + g];
                    mma8(o[nt], a, b0, b1);
                }
            }
            __syncthreads();
        }
        float inv0 = 1.0f / lrow0, inv1 = 1.0f / lrow1;
        float* ob  = outp + ((size_t)(b * TT + qi * 128 + r0)) * DD + h * HD;
        float* ob1 = ob + 8 * DD;
        #pragma unroll
        for (int nt = 0; nt < 8; nt++) {
            *(float2*)(ob  + nt*8 + 2*tig) = make_float2(o[nt][0]*inv0, o[nt][1]*inv0);
            *(float2*)(ob1 + nt*8 + 2*tig) = make_float2(o[nt][2]*inv1, o[nt][3]*inv1);
        }
        __syncthreads();
    }
}

/* softmax over T with 1/16 scale folded in */
__global__ void __launch_bounds__(256) k_softmax(const float* __restrict__ S,
                                                 float* __restrict__ O) {
    __shared__ float red[8];
    const int row = blockIdx.x, t = threadIdx.x;
    const float* s = S + (size_t)row * TT;
    float* o = O + (size_t)row * TT;
    float v[8]; float mx = -1e30f;
    #pragma unroll
    for (int i = 0; i < 8; i++) { v[i] = s[t + i * 256] * 0.0625f; mx = fmaxf(mx, v[i]); }
    #pragma unroll
    for (int m = 16; m; m >>= 1) mx = fmaxf(mx, __shfl_xor_sync(0xffffffffu, mx, m));
    if ((t & 31) == 0) red[t >> 5] = mx;
    __syncthreads();
    mx = fmaxf(fmaxf(fmaxf(red[0],red[1]), fmaxf(red[2],red[3])),
               fmaxf(fmaxf(red[4],red[5]), fmaxf(red[6],red[7])));
    float sum = 0.0f;
    #pragma unroll
    for (int i = 0; i < 8; i++) { v[i] = expf(v[i] - mx); sum += v[i]; }
    #pragma unroll
    for (int m = 16; m; m >>= 1) sum += __shfl_xor_sync(0xffffffffu, sum, m);
    __syncthreads();
    if ((t & 31) == 0) red[t >> 5] = sum;
    __syncthreads();
    sum = red[0]+red[1]+red[2]+red[3]+red[4]+red[5]+red[6]+red[7];
    float inv = 1.0f / sum;
    #pragma unroll
    for (int i = 0; i < 8; i++) o[t + i * 256] = v[i] * inv;
}

__global__ void __launch_bounds__(256) k_bits(const float* __restrict__ sel,
                                              const float* __restrict__ w,
                                              const float* __restrict__ bia,
                                              float* __restrict__ bits,
                                              float* __restrict__ pairs) {
    int gw = (blockIdx.x * 256 + threadIdx.x) >> 5;
    int lane = threadIdx.x & 31;
    const float* s = sel + (size_t)gw * DD;
    float acc = 0.0f;
    #pragma unroll
    for (int k = 0; k < 8; k++) acc += s[lane + k * 32] * w[lane + k * 32];
    #pragma unroll
    for (int m = 16; m; m >>= 1) acc += __shfl_xor_sync(0xffffffffu, acc, m);
    if (lane == 0) {
        float v = 1.0f / (1.0f + expf(-(acc + bia[0])));
        bits[gw] = v; pairs[gw] = v;
    }
}

__global__ void __launch_bounds__(256) k_scan(const float* __restrict__ bits,
        const float* __restrict__ w1, const float* __restrict__ b1,
        const float* __restrict__ w2, const float* __restrict__ b2,
        const float* __restrict__ w3, const float* __restrict__ b3,
        float* __restrict__ out) {
    __shared__ float W1[192], W2[4096], W3[128], B1[64], B2[64], B3[2];
    __shared__ float H1[4][64], H2[4][64], CR[4];
    const int t = threadIdx.x;
    for (int i = t; i < 192;  i += 256) W1[i] = w1[i];
    for (int i = t; i < 4096; i += 256) W2[i] = w2[i];
    for (int i = t; i < 128;  i += 256) W3[i] = w3[i];
    if (t < 64) { B1[t] = b1[t]; B2[t] = b2[t]; }
    if (t < 2)  B3[t] = b3[t];
    if (t < 4)  CR[t] = 0.0f;
    __syncthreads();
    const int bb = t >> 6, j = t & 63;
    for (int s = 0; s < 64; s++) {
        float z0 = bits[bb * 128 + 2 * s];
        float z1 = bits[bb * 128 + 2 * s + 1];
        float z2 = CR[bb];
        float h1 = fmaxf(0.0f, z0 * W1[j] + z1 * W1[64 + j] + z2 * W1[128 + j] + B1[j]);
        H1[bb][j] = h1;
        __syncthreads();
        float acc = B2[j];
        #pragma unroll 8
        for (int i = 0; i < 64; i++) acc += H1[bb][i] * W2[i * 64 + j];
        H2[bb][j] = fmaxf(0.0f, acc);
        __syncthreads();
        if (j < 2) {
            float a = B3[j];
            #pragma unroll 8
            for (int i = 0; i < 64; i++) a += H2[bb][i] * W3[i * 2 + j];
            float ov = 1.0f / (1.0f + expf(-a));
            if (j == 0) out[bb * 65 + s] = ov;
            else        CR[bb] = ov;
        }
        __syncthreads();
    }
    if (t < 4) out[t * 65 + 64] = CR[t];
}

extern "C" void kernel_launch(void* const* d_in, const int* in_sizes, int n_in,
                              void* d_out, int out_size) {
    const int*   tokens = (const int*)  d_in[0];
    const float* embed  = (const float*)d_in[1];
    const float* ln1w = (const float*)d_in[2];
    const float* ln1b = (const float*)d_in[3];
    const float* qkvw = (const float*)d_in[4];
    const float* qkvb = (const float*)d_in[5];
    const float* projw= (const float*)d_in[6];
    const float* projb= (const float*)d_in[7];
    const float* ln2w = (const float*)d_in[8];
    const float* ln2b = (const float*)d_in[9];
    const float* f1w  = (const float*)d_in[10];
    const float* f1b  = (const float*)d_in[11];
    const float* f2w  = (const float*)d_in[12];
    const float* f2b  = (const float*)d_in[13];
    const float* lnfw = (const float*)d_in[14];
    const float* lnfb = (const float*)d_in[15];
    const float* oq   = (const float*)d_in[16];
    const float* opw  = (const float*)d_in[17];
    const float* opb  = (const float*)d_in[18];
    const float* mw1  = (const float*)d_in[19];
    const float* mb1  = (const float*)d_in[20];
    const float* mw2  = (const float*)d_in[21];
    const float* mb2  = (const float*)d_in[22];
    const float* mw3  = (const float*)d_in[23];
    const float* mb3  = (const float*)d_in[24];
    float* out = (float*)d_out;
    float* out_pairs = out + BB * 65;
    float* out_qattn = out + BB * 65 + BB * NQ;

    float *x,*lnb,*qkv,*att,*ffh,*sel,*bits,*zero;
    cudaGetSymbolAddress((void**)&x,   g_x);
    cudaGetSymbolAddress((void**)&lnb, g_lnb);
    cudaGetSymbolAddress((void**)&qkv, g_qkv);
    cudaGetSymbolAddress((void**)&att, g_att);
    cudaGetSymbolAddress((void**)&ffh, g_ffh);
    cudaGetSymbolAddress((void**)&sel, g_sel);
    cudaGetSymbolAddress((void**)&bits,g_bits);
    cudaGetSymbolAddress((void**)&zero,g_zero);
    cudaFuncSetAttribute(k_attn_tc, cudaFuncAttributeMaxDynamicSharedMemorySize, ATTC_SMEM);
    cudaFuncSetAttribute(k_gemm_tc<0,128>, cudaFuncAttributeMaxDynamicSharedMemorySize, GS(128));
    cudaFuncSetAttribute(k_gemm_tc<1,128>, cudaFuncAttributeMaxDynamicSharedMemorySize, GS(128));
    cudaFuncSetAttribute(k_gemm_tc<2,64>,  cudaFuncAttributeMaxDynamicSharedMemorySize, GS(64));
    cudaFuncSetAttribute(k_gemm_tc<0,64>,  cudaFuncAttributeMaxDynamicSharedMemorySize, GS(64));

    k_init_tab<<<1, 32>>>();
    k_embed<<<(MMR * DD) / 256, 256>>>(tokens, embed, x);

    for (int l = 0; l < LL; l++) {
        k_ln<<<MMR / 8, 256>>>(x, ln1w + l * DD, ln1b + l * DD, lnb);
        k_gemm_tc<0,128><<<dim3(6, 64, 1), 256, GS(128)>>>(lnb,
            qkvw + (size_t)l * DD * 3 * DD, qkvb + l * 3 * DD, (const float*)0,
            qkv, 3 * DD, DD, 0, 0, 0);
        k_rope<<<(MMR * 128) / 256, 256>>>(qkv);
        k_attn_tc<<<dim3(8, BB * 4), 256, ATTC_SMEM>>>(qkv, att);
        k_gemm_tc<2,64><<<dim3(2, 128, 1), 256, GS(64)>>>(att,
            projw + (size_t)l * DD * DD, projb + l * DD, x, x, DD, DD, 0, 0, 0);
        k_ln<<<MMR / 8, 256>>>(x, ln2w + l * DD, ln2b + l * DD, lnb);
        k_gemm_tc<1,128><<<dim3(8, 64, 1), 256, GS(128)>>>(lnb,
            f1w + (size_t)l * DD * 4 * DD, f1b + (size_t)l * 4 * DD, (const float*)0,
            ffh, 4 * DD, DD, 0, 0, 0);
        k_gemm_tc<2,64><<<dim3(2, 128, 1), 256, GS(64)>>>(ffh,
            f2w + (size_t)l * 4 * DD * DD, f2b + l * DD, x, x, DD, 4 * DD, 0, 0, 0);
    }

    k_ln<<<MMR / 8, 256>>>(x, lnfw, lnfb, lnb);
    k_tr<<<dim3(TT / 32, DD / 32, BB), 256>>>(lnb, qkv);
    k_gemm_tc<0,64><<<dim3(TT / 128, NQ / 64, BB), 256, GS(64)>>>(oq, qkv, zero,
        (const float*)0, ffh, TT, DD, 0, (long long)DD * TT, (long long)NQ * TT);
    k_softmax<<<BB * NQ, 256>>>(ffh, out_qattn);
    k_gemm_tc<0,64><<<dim3(DD / 128, NQ / 64, BB), 256, GS(64)>>>(out_qattn, lnb, zero,
        (const float*)0, sel, DD, TT, (long long)NQ * TT, (long long)TT * DD,
        (long long)NQ * DD);
    k_bits<<<(BB * NQ * 32) / 256, 256>>>(sel, opw, opb, bits, out_pairs);
    k_scan<<<1, 256>>>(bits, mw1, mb1, mw2, mb2, mw3, mb3, out);
}

// round 17
// speedup vs baseline: 1.0870x; 1.0870x over previous
#include <cuda_runtime.h>
#include <math.h>

#define BB 4
#define TT 2048
#define DD 256
#define HD 64
#define LL 2
#define MMR (BB*TT)
#define NQ 128

__device__ __align__(16) float g_x  [MMR*DD];
__device__ __align__(16) float g_lnb[MMR*DD];
__device__ __align__(16) float g_qkv[MMR*3*DD];
__device__ __align__(16) float g_att[MMR*DD];
__device__ __align__(16) float g_ffh[MMR*4*DD];
__device__ __align__(16) float g_sel[BB*NQ*DD];
__device__ __align__(16) float g_bits[BB*NQ];
__device__ __align__(16) float g_zero[TT];
__device__ float g_invf[32];

__device__ __forceinline__ float geluf(float v) {
    return 0.5f * v * (1.0f + erff(v * 0.70710678118654752f));
}

__device__ __forceinline__ void cp16(void* smem_dst, const void* gsrc) {
    unsigned s = (unsigned)__cvta_generic_to_shared(smem_dst);
    asm volatile("cp.async.cg.shared.global [%0], [%1], 16;" :: "r"(s), "l"(gsrc));
}
#define CP_COMMIT() asm volatile("cp.async.commit_group;")
#define CP_WAIT0()  asm volatile("cp.async.wait_group 0;")
#define CP_WAIT1()  asm volatile("cp.async.wait_group 1;")

__device__ __forceinline__ void mma8(float* d, const unsigned* a, unsigned b0, unsigned b1) {
    asm volatile(
        "mma.sync.aligned.m16n8k8.row.col.f32.tf32.tf32.f32 "
        "{%0,%1,%2,%3},{%4,%5,%6,%7},{%8,%9},{%0,%1,%2,%3};"
        : "+f"(d[0]), "+f"(d[1]), "+f"(d[2]), "+f"(d[3])
        : "r"(a[0]), "r"(a[1]), "r"(a[2]), "r"(a[3]), "r"(b0), "r"(b1));
}

__global__ void k_init_tab() {
    int t = threadIdx.x;
    g_invf[t] = (float)exp(-0.28782313662425572 * (double)t);
}

__global__ void __launch_bounds__(256) k_embed(const int* __restrict__ tok,
                                               const float* __restrict__ emb,
                                               float* __restrict__ x) {
    int i = blockIdx.x * 256 + threadIdx.x;
    x[i] = emb[tok[i >> 8] * DD + (i & 255)];
}

/* warp-per-row layernorm */
__global__ void __launch_bounds__(256) k_ln(const float* __restrict__ x,
                                            const float* __restrict__ w,
                                            const float* __restrict__ bia,
                                            float* __restrict__ y) {
    const int warp = threadIdx.x >> 5, lane = threadIdx.x & 31;
    const int row = blockIdx.x * 8 + warp;
    const float* xr = x + (size_t)row * DD;
    float4 v0 = *(const float4*)(xr + lane * 4);
    float4 v1 = *(const float4*)(xr + 128 + lane * 4);
    float s = v0.x+v0.y+v0.z+v0.w + v1.x+v1.y+v1.z+v1.w;
    #pragma unroll
    for (int m = 16; m; m >>= 1) s += __shfl_xor_sync(0xffffffffu, s, m);
    float mean = s * (1.0f / DD);
    float a0 = v0.x-mean, a1 = v0.y-mean, a2 = v0.z-mean, a3 = v0.w-mean;
    float a4 = v1.x-mean, a5 = v1.y-mean, a6 = v1.z-mean, a7 = v1.w-mean;
    float q = a0*a0+a1*a1+a2*a2+a3*a3+a4*a4+a5*a5+a6*a6+a7*a7;
    #pragma unroll
    for (int m = 16; m; m >>= 1) q += __shfl_xor_sync(0xffffffffu, q, m);
    float rs = rsqrtf(q * (1.0f / DD) + 1e-5f);
    float4 w0 = *(const float4*)(w + lane * 4);
    float4 w1 = *(const float4*)(w + 128 + lane * 4);
    float4 b0 = *(const float4*)(bia + lane * 4);
    float4 b1 = *(const float4*)(bia + 128 + lane * 4);
    float* yr = y + (size_t)row * DD;
    *(float4*)(yr + lane * 4) =
        make_float4(a0*rs*w0.x+b0.x, a1*rs*w0.y+b0.y, a2*rs*w0.z+b0.z, a3*rs*w0.w+b0.w);
    *(float4*)(yr + 128 + lane * 4) =
        make_float4(a4*rs*w1.x+b1.x, a5*rs*w1.y+b1.y, a6*rs*w1.z+b1.z, a7*rs*w1.w+b1.w);
}

/* transpose [T,D] -> [D,T] per batch */
__global__ void __launch_bounds__(256) k_tr(const float* __restrict__ A,
                                            float* __restrict__ B) {
    __shared__ float t[32][33];
    const float* Ab = A + (size_t)blockIdx.z * TT * DD;
    float* Bb = B + (size_t)blockIdx.z * DD * TT;
    int t0 = blockIdx.x * 32, d0 = blockIdx.y * 32;
    int x = threadIdx.x & 31, y = threadIdx.x >> 5;
    #pragma unroll
    for (int i = 0; i < 32; i += 8)
        t[y + i][x] = Ab[(size_t)(t0 + y + i) * DD + d0 + x];
    __syncthreads();
    #pragma unroll
    for (int i = 0; i < 32; i += 8)
        Bb[(size_t)(d0 + y + i) * TT + t0 + x] = t[x][y + i];
}

/* ---- tf32 tensor-core GEMM, 2-stage cp.async (R12 schedule), batched ---- */
#define GS(TM) ((2 * ((TM)*36 + 32*136)) * 4)
template<int EPI, int TM>
__global__ void __launch_bounds__(256, 2) k_gemm_tc(
        const float* __restrict__ A, const float* __restrict__ W,
        const float* __restrict__ bias, const float* __restrict__ res,
        float* __restrict__ C, int N, int K,
        long long sA, long long sW, long long sC) {
    A += (long long)blockIdx.z * sA;
    W += (long long)blockIdx.z * sW;
    C += (long long)blockIdx.z * sC;
    extern __shared__ unsigned sg[];
    const int GA_W = TM * 36, GW_W = 32 * 136;
    unsigned* As0 = sg;
    unsigned* Ws0 = sg + 2 * GA_W;
    const int m0 = blockIdx.y * TM, n0 = blockIdx.x * 128;
    constexpr int MI = TM / 32;
    float d[MI * 4][4] = {};
    const int tid = threadIdx.x, warp = tid >> 5, lane = tid & 31;
    const int g = lane >> 2, tig = lane & 3;
    const int wm = (warp & 1) * (TM / 2), wn = (warp >> 1) * 32;
    const int cw = lane * 4;

    const int T = K >> 5;
    #pragma unroll
    for (int it = 0; it < TM / 32; it++) {
        int r = (TM == 128) ? (warp * 16 + (lane >> 3) + it * 4) : ((tid >> 3) + it * 32);
        int ca = (TM == 128) ? ((lane & 7) * 4) : ((tid & 7) * 4);
        cp16(&As0[r * 36 + ca], A + (size_t)(m0 + r) * K + ca);
    }
    #pragma unroll
    for (int it = 0; it < 4; it++) {
        int kw = warp + it * 8;
        cp16(&Ws0[kw * 136 + cw], W + (size_t)kw * N + n0 + cw);
    }
    CP_COMMIT();
    for (int t = 0; t < T; t++) {
        if (t + 1 < T) {
            int k0 = (t + 1) << 5, st = (t + 1) & 1;
            #pragma unroll
            for (int it = 0; it < TM / 32; it++) {
                int r = (TM == 128) ? (warp * 16 + (lane >> 3) + it * 4) : ((tid >> 3) + it * 32);
                int ca = (TM == 128) ? ((lane & 7) * 4) : ((tid & 7) * 4);
                cp16(&As0[st * GA_W + r * 36 + ca], A + (size_t)(m0 + r) * K + k0 + ca);
            }
            #pragma unroll
            for (int it = 0; it < 4; it++) {
                int kw = warp + it * 8;
                cp16(&Ws0[st * GW_W + kw * 136 + cw], W + (size_t)(k0 + kw) * N + n0 + cw);
            }
            CP_COMMIT();
            CP_WAIT1();
        } else {
            CP_WAIT0();
        }
        __syncthreads();
        const unsigned* Ab = As0 + (t & 1) * GA_W;
        const unsigned* Wb = Ws0 + (t & 1) * GW_W;
        #pragma unroll
        for (int ks = 0; ks < 32; ks += 8) {
            unsigned a[MI][4], b[4][2];
            #pragma unroll
            for (int mi = 0; mi < MI; mi++) {
                int m = wm + mi * 16 + g;
                a[mi][0] = Ab[m * 36 + ks + tig];
                a[mi][1] = Ab[(m + 8) * 36 + ks + tig];
                a[mi][2] = Ab[m * 36 + ks + tig + 4];
                a[mi][3] = Ab[(m + 8) * 36 + ks + tig + 4];
            }
            #pragma unroll
            for (int ni = 0; ni < 4; ni++) {
                int n = wn + ni * 8 + g;
                b[ni][0] = Wb[(ks + tig) * 136 + n];
                b[ni][1] = Wb[(ks + tig + 4) * 136 + n];
            }
            #pragma unroll
            for (int mi = 0; mi < MI; mi++)
                #pragma unroll
                for (int ni = 0; ni < 4; ni++)
                    mma8(d[mi * 4 + ni], a[mi], b[ni][0], b[ni][1]);
        }
        __syncthreads();
    }
    #pragma unroll
    for (int mi = 0; mi < MI; mi++) {
        #pragma unroll
        for (int ni = 0; ni < 4; ni++) {
            float* dd = d[mi * 4 + ni];
            int col = n0 + wn + ni * 8 + 2 * tig;
            int r0 = m0 + wm + mi * 16 + g;
            float2 b2 = *(const float2*)(bias + col);
            float2 v0 = make_float2(dd[0] + b2.x, dd[1] + b2.y);
            float2 v1 = make_float2(dd[2] + b2.x, dd[3] + b2.y);
            if (EPI == 1) {
                v0.x = geluf(v0.x); v0.y = geluf(v0.y);
                v1.x = geluf(v1.x); v1.y = geluf(v1.y);
            }
            if (EPI == 2) {
                float2 r0v = *(const float2*)(res + (size_t)r0 * N + col);
                float2 r1v = *(const float2*)(res + (size_t)(r0 + 8) * N + col);
                v0.x += r0v.x; v0.y += r0v.y;
                v1.x += r1v.x; v1.y += r1v.y;
            }
            *(float2*)(C + (size_t)r0 * N + col) = v0;
            *(float2*)(C + (size_t)(r0 + 8) * N + col) = v1;
        }
    }
}

/* ---- split-K GEMM for selected: P[z] += A_b[.,sp-slice] @ W_b[sp-slice,.]
   z = b*8+sp ; A rows NQ lda TT ; W rows DD-wide ; 64x128 tile, K=256 slice */
__global__ void __launch_bounds__(256, 2) k_gemm_sk(
        const float* __restrict__ A0, const float* __restrict__ W0,
        float* __restrict__ P) {
    const int b = blockIdx.z >> 3, sp = blockIdx.z & 7;
    const float* A = A0 + (size_t)b * NQ * TT + sp * 256;
    const float* W = W0 + (size_t)b * TT * DD + (size_t)sp * 256 * DD;
    float* C = P + (size_t)blockIdx.z * NQ * DD;
    extern __shared__ unsigned sg[];
    const int GA_W = 64 * 36, GW_W = 32 * 136;
    unsigned* As0 = sg;
    unsigned* Ws0 = sg + 2 * GA_W;
    const int m0 = blockIdx.y * 64, n0 = blockIdx.x * 128;
    float d[8][4] = {};
    const int tid = threadIdx.x, warp = tid >> 5, lane = tid & 31;
    const int g = lane >> 2, tig = lane & 3;
    const int wm = (warp & 1) * 32, wn = (warp >> 1) * 32;
    const int cw = lane * 4;
    const int ar = tid >> 3, ac = (tid & 7) * 4;

    #pragma unroll
    for (int it = 0; it < 2; it++)
        cp16(&As0[(ar + it * 32) * 36 + ac], A + (size_t)(m0 + ar + it * 32) * TT + ac);
    #pragma unroll
    for (int it = 0; it < 4; it++) {
        int kw = warp + it * 8;
        cp16(&Ws0[kw * 136 + cw], W + (size_t)kw * DD + n0 + cw);
    }
    CP_COMMIT();
    for (int t = 0; t < 8; t++) {
        if (t + 1 < 8) {
            int k0 = (t + 1) << 5, st = (t + 1) & 1;
            #pragma unroll
            for (int it = 0; it < 2; it++)
                cp16(&As0[st * GA_W + (ar + it * 32) * 36 + ac],
                     A + (size_t)(m0 + ar + it * 32) * TT + k0 + ac);
            #pragma unroll
            for (int it = 0; it < 4; it++) {
                int kw = warp + it * 8;
                cp16(&Ws0[st * GW_W + kw * 136 + cw], W + (size_t)(k0 + kw) * DD + n0 + cw);
            }
            CP_COMMIT();
            CP_WAIT1();
        } else {
            CP_WAIT0();
        }
        __syncthreads();
        const unsigned* Ab = As0 + (t & 1) * GA_W;
        const unsigned* Wb = Ws0 + (t & 1) * GW_W;
        #pragma unroll
        for (int ks = 0; ks < 32; ks += 8) {
            unsigned a[2][4], bfr[4][2];
            #pragma unroll
            for (int mi = 0; mi < 2; mi++) {
                int m = wm + mi * 16 + g;
                a[mi][0] = Ab[m * 36 + ks + tig];
                a[mi][1] = Ab[(m + 8) * 36 + ks + tig];
                a[mi][2] = Ab[m * 36 + ks + tig + 4];
                a[mi][3] = Ab[(m + 8) * 36 + ks + tig + 4];
            }
            #pragma unroll
            for (int ni = 0; ni < 4; ni++) {
                int n = wn + ni * 8 + g;
                bfr[ni][0] = Wb[(ks + tig) * 136 + n];
                bfr[ni][1] = Wb[(ks + tig + 4) * 136 + n];
            }
            #pragma unroll
            for (int mi = 0; mi < 2; mi++)
                #pragma unroll
                for (int ni = 0; ni < 4; ni++)
                    mma8(d[mi * 4 + ni], a[mi], bfr[ni][0], bfr[ni][1]);
        }
        __syncthreads();
    }
    #pragma unroll
    for (int mi = 0; mi < 2; mi++) {
        #pragma unroll
        for (int ni = 0; ni < 4; ni++) {
            float* dd = d[mi * 4 + ni];
            int col = n0 + wn + ni * 8 + 2 * tig;
            int r0 = m0 + wm + mi * 16 + g;
            *(float2*)(C + (size_t)r0 * DD + col) = make_float2(dd[0], dd[1]);
            *(float2*)(C + (size_t)(r0 + 8) * DD + col) = make_float2(dd[2], dd[3]);
        }
    }
}

/* reduce 8 split-K partials: sel[b][r] = sum_s P[b*8+s][r] */
__global__ void __launch_bounds__(256) k_red(const float* __restrict__ P,
                                             float* __restrict__ sel) {
    int i = blockIdx.x * 256 + threadIdx.x;      /* over BB*NQ*DD */
    int b = i / (NQ * DD), r = i % (NQ * DD);
    const float* p = P + (size_t)b * 8 * NQ * DD + r;
    float s = 0.0f;
    #pragma unroll
    for (int k = 0; k < 8; k++) s += p[(size_t)k * NQ * DD];
    sel[i] = s;
}

__global__ void __launch_bounds__(256) k_rope(float* __restrict__ qkv) {
    int i = blockIdx.x * 256 + threadIdx.x;
    int p = i & 31, h = (i >> 5) & 3, bt = i >> 7;
    int tpos = bt & (TT - 1);
    float ang = (float)tpos * g_invf[p], sn, cs;
    sincosf(ang, &sn, &cs);
    size_t base = (size_t)bt * (3 * DD) + h * HD;
    float q1 = qkv[base + p],       q2 = qkv[base + 32 + p];
    qkv[base + p]      = q1 * cs - q2 * sn;
    qkv[base + 32 + p] = q2 * cs + q1 * sn;
    float k1 = qkv[base + 256 + p], k2 = qkv[base + 288 + p];
    qkv[base + 256 + p] = k1 * cs - k2 * sn;
    qkv[base + 288 + p] = k2 * cs + k1 * sn;
}

/* ---- tf32 flash attention (R14 proven version): 64-row q-tiles ---- */
#define QST 68
#define VST 72
#define ATT_Q  0
#define ATT_P  (64*QST)
#define ATT_K  (2*64*QST)
#define ATT_V  (ATT_K + 2*64*QST)
#define ATTC_SMEM ((ATT_V + 2*64*VST) * 4)
__global__ void __launch_bounds__(128) k_attn_tc(const float* __restrict__ qkv,
                                                 float* __restrict__ outp) {
    extern __shared__ unsigned smu[];
    unsigned* Qs = smu + ATT_Q;
    unsigned* Ps = smu + ATT_P;
    unsigned* Ks = smu + ATT_K;
    unsigned* Vs = smu + ATT_V;
    const int pp = blockIdx.x;
    const int b = blockIdx.y >> 2, h = blockIdx.y & 3;
    const int tid = threadIdx.x, warp = tid >> 5, lane = tid & 31;
    const int g = lane >> 2, tig = lane & 3;
    const int wm = warp * 16;
    const int r0 = wm + g, r1 = wm + g + 8;
    const size_t ROW = 3 * DD;
    const int lr = tid >> 4, lc4 = (tid & 15) << 2;

    for (int qsel = 0; qsel < 2; qsel++) {
        const int qi = qsel ? (31 - pp) : pp;
        const float* qb = qkv + ((size_t)(b * TT + qi * 64)) * ROW + h * HD;
        #pragma unroll
        for (int it = 0; it < 8; it++) {
            int r = lr + it * 8;
            cp16(&Qs[r * QST + lc4], qb + (size_t)r * ROW + lc4);
        }
        CP_COMMIT();
        {
            const float* kbp = qkv + ((size_t)(b * TT)) * ROW + DD + h * HD;
            #pragma unroll
            for (int it = 0; it < 8; it++) {
                int r = lr + it * 8;
                cp16(&Ks[r * QST + lc4], kbp + (size_t)r * ROW + lc4);
                cp16(&Vs[r * VST + lc4], kbp + DD + (size_t)r * ROW + lc4);
            }
            CP_COMMIT();
        }
        float o[8][4] = {};
        float mrow0 = -1e30f, mrow1 = -1e30f, lrow0 = 0.0f, lrow1 = 0.0f;

        for (int kb = 0; kb <= qi; kb++) {
            if (kb + 1 <= qi) {
                const float* kbp = qkv + ((size_t)(b * TT + (kb + 1) * 64)) * ROW + DD + h * HD;
                unsigned* Kd = Ks + ((kb + 1) & 1) * 64 * QST;
                unsigned* Vd = Vs + ((kb + 1) & 1) * 64 * VST;
                #pragma unroll
                for (int it = 0; it < 8; it++) {
                    int r = lr + it * 8;
                    cp16(&Kd[r * QST + lc4], kbp + (size_t)r * ROW + lc4);
                    cp16(&Vd[r * VST + lc4], kbp + DD + (size_t)r * ROW + lc4);
                }
                CP_COMMIT();
                CP_WAIT1();
            } else {
                CP_WAIT0();
            }
            __syncthreads();
            const unsigned* Kb = Ks + (kb & 1) * 64 * QST;
            const unsigned* Vb = Vs + (kb & 1) * 64 * VST;

            float s[8][4] = {};
            #pragma unroll
            for (int ks = 0; ks < 64; ks += 8) {
                unsigned a[4];
                a[0] = Qs[r0 * QST + ks + tig];
                a[1] = Qs[r1 * QST + ks + tig];
                a[2] = Qs[r0 * QST + ks + tig + 4];
                a[3] = Qs[r1 * QST + ks + tig + 4];
                #pragma unroll
                for (int nt = 0; nt < 8; nt++) {
                    unsigned b0 = Kb[(nt*8 + g) * QST + ks + tig];
                    unsigned b1 = Kb[(nt*8 + g) * QST + ks + tig + 4];
                    mma8(s[nt], a, b0, b1);
                }
            }

            const bool diag = (kb == qi);
            #pragma unroll
            for (int nt = 0; nt < 8; nt++) {
                int c0 = nt * 8 + 2 * tig, c1 = c0 + 1;
                s[nt][0] *= 0.125f; s[nt][1] *= 0.125f;
                s[nt][2] *= 0.125f; s[nt][3] *= 0.125f;
                if (diag) {
                    if (c0 > r0) s[nt][0] = -1e30f;
                    if (c1 > r0) s[nt][1] = -1e30f;
                    if (c0 > r1) s[nt][2] = -1e30f;
                    if (c1 > r1) s[nt][3] = -1e30f;
                }
            }
            float rm0 = -1e30f, rm1 = -1e30f;
            #pragma unroll
            for (int nt = 0; nt < 8; nt++) {
                rm0 = fmaxf(rm0, fmaxf(s[nt][0], s[nt][1]));
                rm1 = fmaxf(rm1, fmaxf(s[nt][2], s[nt][3]));
            }
            rm0 = fmaxf(rm0, __shfl_xor_sync(0xffffffffu, rm0, 1));
            rm0 = fmaxf(rm0, __shfl_xor_sync(0xffffffffu, rm0, 2));
            rm1 = fmaxf(rm1, __shfl_xor_sync(0xffffffffu, rm1, 1));
            rm1 = fmaxf(rm1, __shfl_xor_sync(0xffffffffu, rm1, 2));
            float mn0 = fmaxf(mrow0, rm0), mn1 = fmaxf(mrow1, rm1);
            float corr0 = __expf(mrow0 - mn0), corr1 = __expf(mrow1 - mn1);
            float rs0 = 0.0f, rs1 = 0.0f;
            #pragma unroll
            for (int nt = 0; nt < 8; nt++) {
                s[nt][0] = __expf(s[nt][0] - mn0); rs0 += s[nt][0];
                s[nt][1] = __expf(s[nt][1] - mn0); rs0 += s[nt][1];
                s[nt][2] = __expf(s[nt][2] - mn1); rs1 += s[nt][2];
                s[nt][3] = __expf(s[nt][3] - mn1); rs1 += s[nt][3];
            }
            rs0 += __shfl_xor_sync(0xffffffffu, rs0, 1);
            rs0 += __shfl_xor_sync(0xffffffffu, rs0, 2);
            rs1 += __shfl_xor_sync(0xffffffffu, rs1, 1);
            rs1 += __shfl_xor_sync(0xffffffffu, rs1, 2);
            lrow0 = lrow0 * corr0 + rs0;
            lrow1 = lrow1 * corr1 + rs1;
            mrow0 = mn0; mrow1 = mn1;
            #pragma unroll
            for (int nt = 0; nt < 8; nt++) {
                o[nt][0] *= corr0; o[nt][1] *= corr0;
                o[nt][2] *= corr1; o[nt][3] *= corr1;
            }
            #pragma unroll
            for (int nt = 0; nt < 8; nt++) {
                Ps[r0 * QST + nt*8 + 2*tig]     = __float_as_uint(s[nt][0]);
                Ps[r0 * QST + nt*8 + 2*tig + 1] = __float_as_uint(s[nt][1]);
                Ps[r1 * QST + nt*8 + 2*tig]     = __float_as_uint(s[nt][2]);
                Ps[r1 * QST + nt*8 + 2*tig + 1] = __float_as_uint(s[nt][3]);
            }
            __syncwarp();
            #pragma unroll
            for (int ks = 0; ks < 64; ks += 8) {
                unsigned a[4];
                a[0] = Ps[r0 * QST + ks + tig];
                a[1] = Ps[r1 * QST + ks + tig];
                a[2] = Ps[r0 * QST + ks + tig + 4];
                a[3] = Ps[r1 * QST + ks + tig + 4];
                #pragma unroll
                for (int nt = 0; nt < 8; nt++) {
                    unsigned b0 = Vb[(ks + tig) * VST + nt*8 + g];
                    unsigned b1 = Vb[(ks + tig + 4) * VST + nt*8 + g];
                    mma8(o[nt], a, b0, b1);
                }
            }
            __syncthreads();
        }
        float inv0 = 1.0f / lrow0, inv1 = 1.0f / lrow1;
        float* ob  = outp + ((size_t)(b * TT + qi * 64 + r0)) * DD + h * HD;
        float* ob1 = ob + 8 * DD;
        #pragma unroll
        for (int nt = 0; nt < 8; nt++) {
            *(float2*)(ob  + nt*8 + 2*tig) = make_float2(o[nt][0]*inv0, o[nt][1]*inv0);
            *(float2*)(ob1 + nt*8 + 2*tig) = make_float2(o[nt][2]*inv1, o[nt][3]*inv1);
        }
        __syncthreads();
    }
}

/* softmax over T with 1/16 scale folded in */
__global__ void __launch_bounds__(256) k_softmax(const float* __restrict__ S,
                                                 float* __restrict__ O) {
    __shared__ float red[8];
    const int row = blockIdx.x, t = threadIdx.x;
    const float* s = S + (size_t)row * TT;
    float* o = O + (size_t)row * TT;
    float v[8]; float mx = -1e30f;
    #pragma unroll
    for (int i = 0; i < 8; i++) { v[i] = s[t + i * 256] * 0.0625f; mx = fmaxf(mx, v[i]); }
    #pragma unroll
    for (int m = 16; m; m >>= 1) mx = fmaxf(mx, __shfl_xor_sync(0xffffffffu, mx, m));
    if ((t & 31) == 0) red[t >> 5] = mx;
    __syncthreads();
    mx = fmaxf(fmaxf(fmaxf(red[0],red[1]), fmaxf(red[2],red[3])),
               fmaxf(fmaxf(red[4],red[5]), fmaxf(red[6],red[7])));
    float sum = 0.0f;
    #pragma unroll
    for (int i = 0; i < 8; i++) { v[i] = expf(v[i] - mx); sum += v[i]; }
    #pragma unroll
    for (int m = 16; m; m >>= 1) sum += __shfl_xor_sync(0xffffffffu, sum, m);
    __syncthreads();
    if ((t & 31) == 0) red[t >> 5] = sum;
    __syncthreads();
    sum = red[0]+red[1]+red[2]+red[3]+red[4]+red[5]+red[6]+red[7];
    float inv = 1.0f / sum;
    #pragma unroll
    for (int i = 0; i < 8; i++) o[t + i * 256] = v[i] * inv;
}

__global__ void __launch_bounds__(256) k_bits(const float* __restrict__ sel,
                                              const float* __restrict__ w,
                                              const float* __restrict__ bia,
                                              float* __restrict__ bits,
                                              float* __restrict__ pairs) {
    int gw = (blockIdx.x * 256 + threadIdx.x) >> 5;
    int lane = threadIdx.x & 31;
    const float* s = sel + (size_t)gw * DD;
    float acc = 0.0f;
    #pragma unroll
    for (int k = 0; k < 8; k++) acc += s[lane + k * 32] * w[lane + k * 32];
    #pragma unroll
    for (int m = 16; m; m >>= 1) acc += __shfl_xor_sync(0xffffffffu, acc, m);
    if (lane == 0) {
        float v = 1.0f / (1.0f + expf(-(acc + bia[0])));
        bits[gw] = v; pairs[gw] = v;
    }
}

__global__ void __launch_bounds__(256) k_scan(const float* __restrict__ bits,
        const float* __restrict__ w1, const float* __restrict__ b1,
        const float* __restrict__ w2, const float* __restrict__ b2,
        const float* __restrict__ w3, const float* __restrict__ b3,
        float* __restrict__ out) {
    __shared__ float W1[192], W2[4096], W3[128], B1[64], B2[64], B3[2];
    __shared__ float H1[4][64], H2[4][64], CR[4];
    const int t = threadIdx.x;
    for (int i = t; i < 192;  i += 256) W1[i] = w1[i];
    for (int i = t; i < 4096; i += 256) W2[i] = w2[i];
    for (int i = t; i < 128;  i += 256) W3[i] = w3[i];
    if (t < 64) { B1[t] = b1[t]; B2[t] = b2[t]; }
    if (t < 2)  B3[t] = b3[t];
    if (t < 4)  CR[t] = 0.0f;
    __syncthreads();
    const int bb = t >> 6, j = t & 63;
    for (int s = 0; s < 64; s++) {
        float z0 = bits[bb * 128 + 2 * s];
        float z1 = bits[bb * 128 + 2 * s + 1];
        float z2 = CR[bb];
        float h1 = fmaxf(0.0f, z0 * W1[j] + z1 * W1[64 + j] + z2 * W1[128 + j] + B1[j]);
        H1[bb][j] = h1;
        __syncthreads();
        float acc = B2[j];
        #pragma unroll 8
        for (int i = 0; i < 64; i++) acc += H1[bb][i] * W2[i * 64 + j];
        H2[bb][j] = fmaxf(0.0f, acc);
        __syncthreads();
        if (j < 2) {
            float a = B3[j];
            #pragma unroll 8
            for (int i = 0; i < 64; i++) a += H2[bb][i] * W3[i * 2 + j];
            float ov = 1.0f / (1.0f + expf(-a));
            if (j == 0) out[bb * 65 + s] = ov;
            else        CR[bb] = ov;
        }
        __syncthreads();
    }
    if (t < 4) out[t * 65 + 64] = CR[t];
}

extern "C" void kernel_launch(void* const* d_in, const int* in_sizes, int n_in,
                              void* d_out, int out_size) {
    const int*   tokens = (const int*)  d_in[0];
    const float* embed  = (const float*)d_in[1];
    const float* ln1w = (const float*)d_in[2];
    const float* ln1b = (const float*)d_in[3];
    const float* qkvw = (const float*)d_in[4];
    const float* qkvb = (const float*)d_in[5];
    const float* projw= (const float*)d_in[6];
    const float* projb= (const float*)d_in[7];
    const float* ln2w = (const float*)d_in[8];
    const float* ln2b = (const float*)d_in[9];
    const float* f1w  = (const float*)d_in[10];
    const float* f1b  = (const float*)d_in[11];
    const float* f2w  = (const float*)d_in[12];
    const float* f2b  = (const float*)d_in[13];
    const float* lnfw = (const float*)d_in[14];
    const float* lnfb = (const float*)d_in[15];
    const float* oq   = (const float*)d_in[16];
    const float* opw  = (const float*)d_in[17];
    const float* opb  = (const float*)d_in[18];
    const float* mw1  = (const float*)d_in[19];
    const float* mb1  = (const float*)d_in[20];
    const float* mw2  = (const float*)d_in[21];
    const float* mb2  = (const float*)d_in[22];
    const float* mw3  = (const float*)d_in[23];
    const float* mb3  = (const float*)d_in[24];
    float* out = (float*)d_out;
    float* out_pairs = out + BB * 65;
    float* out_qattn = out + BB * 65 + BB * NQ;

    float *x,*lnb,*qkv,*att,*ffh,*sel,*bits,*zero;
    cudaGetSymbolAddress((void**)&x,   g_x);
    cudaGetSymbolAddress((void**)&lnb, g_lnb);
    cudaGetSymbolAddress((void**)&qkv, g_qkv);
    cudaGetSymbolAddress((void**)&att, g_att);
    cudaGetSymbolAddress((void**)&ffh, g_ffh);
    cudaGetSymbolAddress((void**)&sel, g_sel);
    cudaGetSymbolAddress((void**)&bits,g_bits);
    cudaGetSymbolAddress((void**)&zero,g_zero);
    float* skp = ffh + 4 * 1024 * 1024;   /* split-K partials: 1M floats, free tail of g_ffh */

    cudaFuncSetAttribute(k_attn_tc, cudaFuncAttributeMaxDynamicSharedMemorySize, ATTC_SMEM);
    cudaFuncSetAttribute(k_gemm_tc<0,128>, cudaFuncAttributeMaxDynamicSharedMemorySize, GS(128));
    cudaFuncSetAttribute(k_gemm_tc<1,128>, cudaFuncAttributeMaxDynamicSharedMemorySize, GS(128));
    cudaFuncSetAttribute(k_gemm_tc<2,64>,  cudaFuncAttributeMaxDynamicSharedMemorySize, GS(64));
    cudaFuncSetAttribute(k_gemm_tc<0,64>,  cudaFuncAttributeMaxDynamicSharedMemorySize, GS(64));
    cudaFuncSetAttribute(k_gemm_sk,        cudaFuncAttributeMaxDynamicSharedMemorySize, GS(64));

    k_init_tab<<<1, 32>>>();
    k_embed<<<(MMR * DD) / 256, 256>>>(tokens, embed, x);

    for (int l = 0; l < LL; l++) {
        k_ln<<<MMR / 8, 256>>>(x, ln1w + l * DD, ln1b + l * DD, lnb);
        k_gemm_tc<0,128><<<dim3(6, 64, 1), 256, GS(128)>>>(lnb,
            qkvw + (size_t)l * DD * 3 * DD, qkvb + l * 3 * DD, (const float*)0,
            qkv, 3 * DD, DD, 0, 0, 0);
        k_rope<<<(MMR * 128) / 256, 256>>>(qkv);
        k_attn_tc<<<dim3(16, BB * 4), 128, ATTC_SMEM>>>(qkv, att);
        k_gemm_tc<2,64><<<dim3(2, 128, 1), 256, GS(64)>>>(att,
            projw + (size_t)l * DD * DD, projb + l * DD, x, x, DD, DD, 0, 0, 0);
        k_ln<<<MMR / 8, 256>>>(x, ln2w + l * DD, ln2b + l * DD, lnb);
        k_gemm_tc<1,128><<<dim3(8, 64, 1), 256, GS(128)>>>(lnb,
            f1w + (size_t)l * DD * 4 * DD, f1b + (size_t)l * 4 * DD, (const float*)0,
            ffh, 4 * DD, DD, 0, 0, 0);
        k_gemm_tc<2,64><<<dim3(2, 128, 1), 256, GS(64)>>>(ffh,
            f2w + (size_t)l * 4 * DD * DD, f2b + l * DD, x, x, DD, 4 * DD, 0, 0, 0);
    }

    k_ln<<<MMR / 8, 256>>>(x, lnfw, lnfb, lnb);
    k_tr<<<dim3(TT / 32, DD / 32, BB), 256>>>(lnb, qkv);
    k_gemm_tc<0,64><<<dim3(TT / 128, NQ / 64, BB), 256, GS(64)>>>(oq, qkv, zero,
        (const float*)0, ffh, TT, DD, 0, (long long)DD * TT, (long long)NQ * TT);
    k_softmax<<<BB * NQ, 256>>>(ffh, out_qattn);
    /* selected via 8-way split-K */
    k_gemm_sk<<<dim3(DD / 128, NQ / 64, BB * 8), 256, GS(64)>>>(out_qattn, lnb, skp);
    k_red<<<(BB * NQ * DD) / 256, 256>>>(skp, sel);
    k_bits<<<(BB * NQ * 32) / 256, 256>>>(sel, opw, opb, bits, out_pairs);
    k_scan<<<1, 256>>>(bits, mw1, mb1, mw2, mb2, mw3, mb3, out);
}